// round 8
// baseline (speedup 1.0000x reference)
#include <cuda_runtime.h>
#include <cuda_bf16.h>
#include <cstdint>
#include <math.h>

#define BATCH   65536
#define NUMC    512
#define DIM     256
#define BM      128
#define BN      64
#define NT      (NUMC/BN)      // 8
#define THREADS 256
#define NBLOCKS (BATCH/BM)     // 512
#define ALPHA   0.05f
#define FINF    3.402823466e38f

// smem byte offsets
#define SAS     0              // A tile bf16 128x256 swizzled       (65536)
#define SB      65536          // B tile bf16 64x256 swizzled        (32768)
#define SCSQ    98304          // 512 f                              (2048)
#define SXSQ    100352         // 128 f                              (512)
#define SMINB   100864         // 128x2 f                            (1024)
#define SDST    101888         // 128 f                              (512)
#define SMEM_TOTAL 102400

__device__ float g_csq[NUMC];
__device__ __align__(16) uint32_t g_cenB[NUMC * DIM / 2];  // bf16x2, [n][k]
__device__ float g_partials[NBLOCKS];

// ---------------- helpers ----------------
__device__ __forceinline__ uint32_t smem_u32(const void* p) {
    uint32_t a;
    asm("{ .reg .u64 t; cvta.to.shared.u64 t, %1; cvt.u32.u64 %0, t; }"
        : "=r"(a) : "l"(p));
    return a;
}
__device__ __forceinline__ uint32_t bf16pair(float lo, float hi) {
    uint32_t r;
    asm("cvt.rn.satfinite.bf16x2.f32 %0, %1, %2;" : "=r"(r) : "f"(hi), "f"(lo));
    return r;
}
__device__ __forceinline__ void mma16816(float c[4], const uint32_t a[4],
                                         uint32_t b0, uint32_t b1) {
    asm volatile(
        "mma.sync.aligned.m16n8k16.row.col.f32.bf16.bf16.f32 "
        "{%0,%1,%2,%3}, {%4,%5,%6,%7}, {%8,%9}, {%0,%1,%2,%3};"
        : "+f"(c[0]), "+f"(c[1]), "+f"(c[2]), "+f"(c[3])
        : "r"(a[0]), "r"(a[1]), "r"(a[2]), "r"(a[3]), "r"(b0), "r"(b1));
}
#define CP_ASYNC16(dst, src) \
    asm volatile("cp.async.cg.shared.global [%0], [%1], 16;" :: "r"(dst), "l"(src))
#define CP_COMMIT()  asm volatile("cp.async.commit_group;" ::: "memory")
#define CP_WAIT0()   asm volatile("cp.async.wait_group 0;" ::: "memory")

// ---------------------------------------------------------------------------
// Kernel 0: center norms (exact fp32) + bf16 copy of centers, [n][k] layout.
// ---------------------------------------------------------------------------
__global__ void prep_kernel(const float* __restrict__ cen) {
    int w    = blockIdx.x * 8 + (threadIdx.x >> 5);
    int lane = threadIdx.x & 31;
    const float2* row = (const float2*)(cen + (size_t)w * DIM);
    float s = 0.f;
    #pragma unroll
    for (int i = 0; i < 4; i++) {
        float2 v = row[lane + 32 * i];
        s += v.x * v.x + v.y * v.y;
        g_cenB[w * (DIM / 2) + lane + 32 * i] = bf16pair(v.x, v.y);
    }
    #pragma unroll
    for (int off = 16; off; off >>= 1)
        s += __shfl_xor_sync(0xffffffffu, s, off);
    if (lane == 0) g_csq[w] = s;
}

// ---------------------------------------------------------------------------
// Kernel 1: bf16 mma.sync GEMM fused with row-min + sqrt + block reduction.
// BM=128 x BN=64 tiles, single-buffered B + register prefetch, occupancy 2.
// 8 warps as 4M x 2N; warp tile 32x32.
// ---------------------------------------------------------------------------
extern __shared__ char smem[];

__global__ void __launch_bounds__(THREADS, 2)
kmeans_main(const float* __restrict__ emb) {
    const uint32_t sb = smem_u32(smem);
    const int tid   = threadIdx.x;
    const int w     = tid >> 5, lane = tid & 31;
    const int tig   = lane & 3, g = lane >> 2;
    const int warpM = w >> 1, warpN = w & 1;
    const int m0    = warpM * 32;
    const uint32_t g16 = (uint32_t)g << 4;

    // per-thread B-tile offsets (8 x 16B per thread per tile)
    uint32_t sts_off[8]; int ldg_off[8];
    #pragma unroll
    for (int s = 0; s < 8; s++) {
        int idx = tid + s * THREADS;
        int n = idx >> 5, c16 = idx & 31;
        sts_off[s] = (uint32_t)(n * 512 + ((c16 ^ (n & 7)) << 4));
        ldg_off[s] = n * 128 + c16 * 4;   // in uint32 units of g_cenB
    }

    // kick off cp.async of B tile 0 (overlaps the A prologue)
    #pragma unroll
    for (int s = 0; s < 8; s++)
        CP_ASYNC16(sb + SB + sts_off[s], (const char*)g_cenB + ldg_off[s] * 4);
    CP_COMMIT();

    // ---- A load: 2 threads/row, fp32 -> bf16, swizzled store, exact xsq ----
    {
        int row = tid >> 1, half = tid & 1;
        const float4* src = (const float4*)emb
                          + (size_t)(blockIdx.x * BM + row) * (DIM / 4) + half * 32;
        char* dstrow = smem + SAS + row * 512;
        const int key = row & 7;
        float xs = 0.f;
        #pragma unroll
        for (int j = 0; j < 32; j++) {
            float4 v = src[j];
            xs += v.x * v.x + v.y * v.y + v.z * v.z + v.w * v.w;
            int c4 = half * 32 + j;
            uint2 pk;
            pk.x = bf16pair(v.x, v.y);
            pk.y = bf16pair(v.z, v.w);
            *(uint2*)(dstrow + (((c4 >> 1) ^ key) << 4) + ((c4 & 1) << 3)) = pk;
        }
        xs += __shfl_xor_sync(0xffffffffu, xs, 1);
        if (!half) ((float*)(smem + SXSQ))[row] = xs;
    }
    ((float*)(smem + SCSQ))[tid]       = g_csq[tid];
    ((float*)(smem + SCSQ))[tid + 256] = g_csq[tid + 256];

    CP_WAIT0();
    __syncthreads();

    // ---- per-thread fragment base addresses (R3-proven layout) ----
    const char* aP[2][2];
    #pragma unroll
    for (int mi = 0; mi < 2; mi++)
        #pragma unroll
        for (int h = 0; h < 2; h++)
            aP[mi][h] = smem + SAS + (m0 + mi * 16 + g + 8 * h) * 512 + 4 * tig;
    uint32_t bOff[4];
    #pragma unroll
    for (int nj = 0; nj < 4; nj++)
        bOff[nj] = (uint32_t)((warpN * 32 + nj * 8 + g) * 512 + 4 * tig);

    const float* csq_s = (const float*)(smem + SCSQ);
    const char*  B     = smem + SB;
    float rm[2][2] = {{FINF, FINF}, {FINF, FINF}};

    for (int t = 0; t < NT; t++) {
        // register prefetch of next B tile (latency hidden under 16 k-steps)
        uint4 pre[8];
        if (t + 1 < NT) {
            const uint4* src = (const uint4*)(g_cenB + (size_t)(t + 1) * BN * 128);
            #pragma unroll
            for (int s = 0; s < 8; s++) pre[s] = src[ldg_off[s] >> 2];
        }

        float c[2][4][4];
        #pragma unroll
        for (int mi = 0; mi < 2; mi++)
            #pragma unroll
            for (int nj = 0; nj < 4; nj++)
                #pragma unroll
                for (int q = 0; q < 4; q++) c[mi][nj][q] = 0.f;

        #pragma unroll
        for (int ks = 0; ks < 16; ks++) {
            const uint32_t ka = ((uint32_t)ks << 5) ^ g16;
            const uint32_t kb = ka ^ 16u;
            uint32_t a[2][4];
            #pragma unroll
            for (int mi = 0; mi < 2; mi++) {
                a[mi][0] = *(const uint32_t*)(aP[mi][0] + ka);
                a[mi][1] = *(const uint32_t*)(aP[mi][1] + ka);
                a[mi][2] = *(const uint32_t*)(aP[mi][0] + kb);
                a[mi][3] = *(const uint32_t*)(aP[mi][1] + kb);
            }
            #pragma unroll
            for (int nj = 0; nj < 4; nj++) {
                uint32_t b0 = *(const uint32_t*)(B + bOff[nj] + ka);
                uint32_t b1 = *(const uint32_t*)(B + bOff[nj] + kb);
                mma16816(c[0][nj], a[0], b0, b1);
                mma16816(c[1][nj], a[1], b0, b1);
            }
        }

        // epilogue: cand = ||c||^2 - 2 x.c ; running min
        #pragma unroll
        for (int mi = 0; mi < 2; mi++)
            #pragma unroll
            for (int nj = 0; nj < 4; nj++) {
                int col = t * BN + warpN * 32 + nj * 8 + 2 * tig;
                float q0 = csq_s[col]     - 2.f * c[mi][nj][0];
                float q1 = csq_s[col + 1] - 2.f * c[mi][nj][1];
                float q2 = csq_s[col]     - 2.f * c[mi][nj][2];
                float q3 = csq_s[col + 1] - 2.f * c[mi][nj][3];
                rm[mi][0] = fminf(rm[mi][0], fminf(q0, q1));
                rm[mi][1] = fminf(rm[mi][1], fminf(q2, q3));
            }

        if (t + 1 < NT) {
            __syncthreads();   // everyone done reading B tile t
            #pragma unroll
            for (int s = 0; s < 8; s++)
                *(uint4*)(smem + SB + sts_off[s]) = pre[s];
            __syncthreads();   // B tile t+1 visible
        }
    }

    // ---- reduction: min across tig lanes, across warpN, then sqrt & sum ----
    float* minb = (float*)(smem + SMINB);
    #pragma unroll
    for (int mi = 0; mi < 2; mi++)
        #pragma unroll
        for (int h = 0; h < 2; h++) {
            float v = rm[mi][h];
            v = fminf(v, __shfl_xor_sync(0xffffffffu, v, 1));
            v = fminf(v, __shfl_xor_sync(0xffffffffu, v, 2));
            if (tig == 0)
                minb[(m0 + mi * 16 + g + 8 * h) * 2 + warpN] = v;
        }
    __syncthreads();
    if (tid < 128) {
        float m  = fminf(minb[2 * tid], minb[2 * tid + 1]);
        float xs = ((float*)(smem + SXSQ))[tid];
        ((float*)(smem + SDST))[tid] = sqrtf(fmaxf(xs + m, 0.f));
    }
    __syncthreads();
    if (tid < 32) {
        const float* d = (const float*)(smem + SDST);
        float v = (d[tid] + d[tid + 32]) + (d[tid + 64] + d[tid + 96]);
        #pragma unroll
        for (int off = 16; off; off >>= 1)
            v += __shfl_xor_sync(0xffffffffu, v, off);
        if (tid == 0) g_partials[blockIdx.x] = v;
    }
}

// ---------------------------------------------------------------------------
// Kernel 2: deterministic tree reduce of 512 block partials -> scalar.
// ---------------------------------------------------------------------------
__global__ void finalize_kernel(float* __restrict__ out) {
    __shared__ float s[512];
    int tid = threadIdx.x;
    s[tid] = g_partials[tid];
    __syncthreads();
    #pragma unroll
    for (int off = 256; off; off >>= 1) {
        if (tid < off) s[tid] += s[tid + off];
        __syncthreads();
    }
    if (tid == 0) out[0] = s[0] * (ALPHA / (float)BATCH);
}

// ---------------------------------------------------------------------------
extern "C" void kernel_launch(void* const* d_in, const int* in_sizes, int n_in,
                              void* d_out, int out_size) {
    const float* emb;
    const float* cen;
    if (in_sizes[0] == BATCH * DIM) {
        emb = (const float*)d_in[0];
        cen = (const float*)d_in[1];
    } else {
        emb = (const float*)d_in[1];
        cen = (const float*)d_in[0];
    }
    float* out = (float*)d_out;

    cudaFuncSetAttribute(kmeans_main,
                         cudaFuncAttributeMaxDynamicSharedMemorySize, SMEM_TOTAL);

    prep_kernel<<<NUMC / 8, 256>>>(cen);
    kmeans_main<<<NBLOCKS, THREADS, SMEM_TOTAL>>>(emb);
    finalize_kernel<<<1, 512>>>(out);
}

// round 10
// speedup vs baseline: 1.0240x; 1.0240x over previous
#include <cuda_runtime.h>
#include <cuda_bf16.h>
#include <cstdint>
#include <math.h>

#define BATCH   65536
#define NUMC    512
#define DIM     256
#define BM      128
#define BN      128
#define NT      2              // centers per CTA = NT*BN = 256
#define THREADS 256
#define NBLOCKS (2 * BATCH / BM)   // 1024: (rowblock, centerhalf)
#define ALPHA   0.05f
#define FINF    3.402823466e38f

// smem byte offsets (same as R3)
#define SAS     0              // A tile bf16 128x256 swizzled       (65536)
#define SB0     65536          // B buf 0                            (65536)
#define SB1     131072         // B buf 1                            (65536)
#define SCSQ    196608         // 256 f                              (1024)
#define SXSQ    197632         // 128 f                              (512)
#define SMINB   198144         // 128x2 f                            (1024)
#define SMEM_TOTAL 199168

__device__ float g_csq[NUMC];
__device__ __align__(16) uint32_t g_cenB[NUMC * DIM / 2];  // bf16x2, [n][k]
__device__ float g_rmin[2 * BATCH];     // per-row partial min, [half][row]
__device__ float g_xsq[BATCH];          // exact ||x||^2 per row
__device__ float g_partials[128];

// ---------------- helpers ----------------
__device__ __forceinline__ uint32_t smem_u32(const void* p) {
    uint32_t a;
    asm("{ .reg .u64 t; cvta.to.shared.u64 t, %1; cvt.u32.u64 %0, t; }"
        : "=r"(a) : "l"(p));
    return a;
}
__device__ __forceinline__ uint32_t bf16pair(float lo, float hi) {
    uint32_t r;
    asm("cvt.rn.satfinite.bf16x2.f32 %0, %1, %2;" : "=r"(r) : "f"(hi), "f"(lo));
    return r;
}
__device__ __forceinline__ void mma16816(float c[4], const uint32_t a[4],
                                         uint32_t b0, uint32_t b1) {
    asm volatile(
        "mma.sync.aligned.m16n8k16.row.col.f32.bf16.bf16.f32 "
        "{%0,%1,%2,%3}, {%4,%5,%6,%7}, {%8,%9}, {%0,%1,%2,%3};"
        : "+f"(c[0]), "+f"(c[1]), "+f"(c[2]), "+f"(c[3])
        : "r"(a[0]), "r"(a[1]), "r"(a[2]), "r"(a[3]), "r"(b0), "r"(b1));
}
#define CP_ASYNC16(dst, src) \
    asm volatile("cp.async.cg.shared.global [%0], [%1], 16;" :: "r"(dst), "l"(src))
#define CP_COMMIT()  asm volatile("cp.async.commit_group;" ::: "memory")
#define CP_WAIT0()   asm volatile("cp.async.wait_group 0;" ::: "memory")

// ---------------------------------------------------------------------------
// Kernel 0: center norms (exact fp32) + bf16 copy of centers, [n][k] layout.
// ---------------------------------------------------------------------------
__global__ void prep_kernel(const float* __restrict__ cen) {
    int w    = blockIdx.x * 8 + (threadIdx.x >> 5);
    int lane = threadIdx.x & 31;
    const float2* row = (const float2*)(cen + (size_t)w * DIM);
    float s = 0.f;
    #pragma unroll
    for (int i = 0; i < 4; i++) {
        float2 v = row[lane + 32 * i];
        s += v.x * v.x + v.y * v.y;
        g_cenB[w * (DIM / 2) + lane + 32 * i] = bf16pair(v.x, v.y);
    }
    #pragma unroll
    for (int off = 16; off; off >>= 1)
        s += __shfl_xor_sync(0xffffffffu, s, off);
    if (lane == 0) g_csq[w] = s;
}

// ---------------------------------------------------------------------------
// Kernel 1: bf16 mma.sync GEMM fused with row-min. Grid = 1024:
// bid = rowblock*2 + chalf; each CTA scans 256 centers (R3 mainloop, NT=2).
// ---------------------------------------------------------------------------
extern __shared__ char smem[];

__device__ __forceinline__ void cp_tile(uint32_t sb_dst, int t512, int tid) {
    const char* src = (const char*)g_cenB + (size_t)t512 * BN * 512;
    #pragma unroll
    for (int s = 0; s < 16; s++) {
        int idx = tid + s * THREADS;
        int n = idx >> 5, c16 = idx & 31;
        uint32_t dst = sb_dst + n * 512 + (uint32_t)((c16 ^ (n & 7)) << 4);
        CP_ASYNC16(dst, src + n * 512 + c16 * 16);
    }
    CP_COMMIT();
}

__global__ void __launch_bounds__(THREADS, 1)
kmeans_main(const float* __restrict__ emb) {
    const uint32_t sb = smem_u32(smem);
    const int tid   = threadIdx.x;
    const int w     = tid >> 5, lane = tid & 31;
    const int tig   = lane & 3, g = lane >> 2;
    const int warpM = w >> 1, warpN = w & 1;
    const int m0    = warpM * 32;
    const uint32_t g16 = (uint32_t)g << 4;

    const int rowblock = blockIdx.x >> 1;
    const int chalf    = blockIdx.x & 1;
    const int row0     = rowblock * BM;
    const int cbase    = chalf * (NT * BN);   // 0 or 256

    // kick off B tile 0 first (overlaps the A prologue)
    cp_tile(sb + SB0, chalf * NT + 0, tid);

    // ---- A load: 2 threads per row, fp32 -> bf16, swizzled store, xsq ----
    {
        int row = tid >> 1, half = tid & 1;
        const float4* src = (const float4*)emb
                          + (size_t)(row0 + row) * (DIM / 4) + half * 32;
        char* dstrow = smem + SAS + row * 512;
        const int key = row & 7;
        float xs = 0.f;
        #pragma unroll
        for (int j = 0; j < 32; j++) {
            float4 v = src[j];
            xs += v.x * v.x + v.y * v.y + v.z * v.z + v.w * v.w;
            int c4 = half * 32 + j;
            uint2 pk;
            pk.x = bf16pair(v.x, v.y);
            pk.y = bf16pair(v.z, v.w);
            *(uint2*)(dstrow + (((c4 >> 1) ^ key) << 4) + ((c4 & 1) << 3)) = pk;
        }
        xs += __shfl_xor_sync(0xffffffffu, xs, 1);
        if (!half) ((float*)(smem + SXSQ))[row] = xs;
    }
    ((float*)(smem + SCSQ))[tid] = g_csq[cbase + tid];

    CP_WAIT0();
    __syncthreads();

    // ---- per-thread fragment base addresses (R3-proven layout) ----
    const char* aP[2][2];
    #pragma unroll
    for (int mi = 0; mi < 2; mi++)
        #pragma unroll
        for (int h = 0; h < 2; h++)
            aP[mi][h] = smem + SAS + (m0 + mi * 16 + g + 8 * h) * 512 + 4 * tig;
    uint32_t bOff[8];
    #pragma unroll
    for (int nj = 0; nj < 8; nj++)
        bOff[nj] = (uint32_t)((warpN * 64 + nj * 8 + g) * 512 + 4 * tig);

    const float* csq_s = (const float*)(smem + SCSQ);
    float rm[2][2] = {{FINF, FINF}, {FINF, FINF}};

    #pragma unroll
    for (int t = 0; t < NT; t++) {
        if (t + 1 < NT)
            cp_tile(sb + (((t + 1) & 1) ? SB1 : SB0), chalf * NT + t + 1, tid);
        const char* B = smem + ((t & 1) ? SB1 : SB0);

        float c[2][8][4];
        #pragma unroll
        for (int mi = 0; mi < 2; mi++)
            #pragma unroll
            for (int nj = 0; nj < 8; nj++)
                #pragma unroll
                for (int q = 0; q < 4; q++) c[mi][nj][q] = 0.f;

        #pragma unroll
        for (int ks = 0; ks < 16; ks++) {
            const uint32_t ka = ((uint32_t)ks << 5) ^ g16;
            const uint32_t kb = ka ^ 16u;
            uint32_t a[2][4];
            #pragma unroll
            for (int mi = 0; mi < 2; mi++) {
                a[mi][0] = *(const uint32_t*)(aP[mi][0] + ka);
                a[mi][1] = *(const uint32_t*)(aP[mi][1] + ka);
                a[mi][2] = *(const uint32_t*)(aP[mi][0] + kb);
                a[mi][3] = *(const uint32_t*)(aP[mi][1] + kb);
            }
            #pragma unroll
            for (int nj = 0; nj < 8; nj++) {
                uint32_t b0 = *(const uint32_t*)(B + bOff[nj] + ka);
                uint32_t b1 = *(const uint32_t*)(B + bOff[nj] + kb);
                mma16816(c[0][nj], a[0], b0, b1);
                mma16816(c[1][nj], a[1], b0, b1);
            }
        }

        // epilogue: cand = ||c||^2 - 2 x.c ; running min
        #pragma unroll
        for (int mi = 0; mi < 2; mi++)
            #pragma unroll
            for (int nj = 0; nj < 8; nj++) {
                int col = t * BN + warpN * 64 + nj * 8 + 2 * tig;
                float q0 = csq_s[col]     - 2.f * c[mi][nj][0];
                float q1 = csq_s[col + 1] - 2.f * c[mi][nj][1];
                float q2 = csq_s[col]     - 2.f * c[mi][nj][2];
                float q3 = csq_s[col + 1] - 2.f * c[mi][nj][3];
                rm[mi][0] = fminf(rm[mi][0], fminf(q0, q1));
                rm[mi][1] = fminf(rm[mi][1], fminf(q2, q3));
            }

        if (t + 1 < NT) { CP_WAIT0(); __syncthreads(); }
    }

    // ---- reduction: min across tig lanes, across warpN, write per-row min --
    float* minb = (float*)(smem + SMINB);
    #pragma unroll
    for (int mi = 0; mi < 2; mi++)
        #pragma unroll
        for (int h = 0; h < 2; h++) {
            float v = rm[mi][h];
            v = fminf(v, __shfl_xor_sync(0xffffffffu, v, 1));
            v = fminf(v, __shfl_xor_sync(0xffffffffu, v, 2));
            if (tig == 0)
                minb[(m0 + mi * 16 + g + 8 * h) * 2 + warpN] = v;
        }
    __syncthreads();
    if (tid < 128) {
        float m = fminf(minb[2 * tid], minb[2 * tid + 1]);
        g_rmin[chalf * BATCH + row0 + tid] = m;
        if (chalf == 0)
            g_xsq[row0 + tid] = ((const float*)(smem + SXSQ))[tid];
    }
}

// ---------------------------------------------------------------------------
// Kernel 2: combine halves, sqrt, per-block partial sums (128 blocks x 512).
// ---------------------------------------------------------------------------
__global__ void combine_kernel() {
    __shared__ float red[16];
    const int row = blockIdx.x * 512 + threadIdx.x;
    float m = fminf(g_rmin[row], g_rmin[BATCH + row]);
    float d = sqrtf(fmaxf(g_xsq[row] + m, 0.f));
    #pragma unroll
    for (int off = 16; off; off >>= 1)
        d += __shfl_xor_sync(0xffffffffu, d, off);
    const int w = threadIdx.x >> 5, lane = threadIdx.x & 31;
    if (lane == 0) red[w] = d;
    __syncthreads();
    if (w == 0) {
        float v = (lane < 16) ? red[lane] : 0.f;
        #pragma unroll
        for (int off = 8; off; off >>= 1)
            v += __shfl_xor_sync(0xffffffffu, v, off);
        if (lane == 0) g_partials[blockIdx.x] = v;
    }
}

// ---------------------------------------------------------------------------
// Kernel 3: deterministic tree reduce of 128 partials -> scalar.
// ---------------------------------------------------------------------------
__global__ void finalize_kernel(float* __restrict__ out) {
    __shared__ float s[128];
    int tid = threadIdx.x;
    s[tid] = g_partials[tid];
    __syncthreads();
    #pragma unroll
    for (int off = 64; off; off >>= 1) {
        if (tid < off) s[tid] += s[tid + off];
        __syncthreads();
    }
    if (tid == 0) out[0] = s[0] * (ALPHA / (float)BATCH);
}

// ---------------------------------------------------------------------------
extern "C" void kernel_launch(void* const* d_in, const int* in_sizes, int n_in,
                              void* d_out, int out_size) {
    const float* emb;
    const float* cen;
    if (in_sizes[0] == BATCH * DIM) {
        emb = (const float*)d_in[0];
        cen = (const float*)d_in[1];
    } else {
        emb = (const float*)d_in[1];
        cen = (const float*)d_in[0];
    }
    float* out = (float*)d_out;

    cudaFuncSetAttribute(kmeans_main,
                         cudaFuncAttributeMaxDynamicSharedMemorySize, SMEM_TOTAL);

    prep_kernel<<<NUMC / 8, 256>>>(cen);
    kmeans_main<<<NBLOCKS, THREADS, SMEM_TOTAL>>>(emb);
    combine_kernel<<<BATCH / 512, 512>>>();
    finalize_kernel<<<1, 128>>>(out);
}